// round 2
// baseline (speedup 1.0000x reference)
#include <cuda_runtime.h>

// CompressionLayer: grouped GEMM
//   y[b,n,o] = relu( sum_k x_chunk[b,n,k] * Wk[n,o,k] + bk[n,o] )
// x: [256,512,512] f32, chunks 16x16 (N=1024, KIN=256), out per chunk 8x8 (KOUT=64)
// out[b, (ch*8+oi)*256 + cw*8+oj], n = ch*32 + cw, k = i*16 + j.
//
// One block per (n, 128-batch tile): 2048 blocks, 256 threads.
// SMEM: W[n] (64x256 f32, quad-XOR swizzled) + X tile (128x256 f32) + bias.
// Thread tile 8 batches x 4 outputs, accumulated as f32x2 over (k,k+1) lanes
// via fma.rn.f32x2 (FFMA2) -- both operands k-contiguous, no packing needed.

#define BT 128          // batches per block
#define NTHREADS 256

__device__ __forceinline__ void fma2(unsigned long long &d,
                                     unsigned long long a,
                                     unsigned long long b) {
    asm volatile("fma.rn.f32x2 %0, %1, %2, %0;" : "+l"(d) : "l"(a), "l"(b));
}

__device__ __forceinline__ float2 unpack2(unsigned long long v) {
    float2 f;
    asm("mov.b64 {%0, %1}, %2;" : "=f"(f.x), "=f"(f.y) : "l"(v));
    return f;
}

// quad-granularity XOR swizzle for W rows: permutes 16B quads within the
// 128B bank-span so 8 threads reading rows o=4*og.. hit distinct bank quads.
__device__ __forceinline__ int swz(int o) { return (((o) >> 2) & 7) << 2; }

__global__ void __launch_bounds__(NTHREADS, 1)
compression_kernel(const float* __restrict__ xg,
                   const float* __restrict__ Wg,
                   const float* __restrict__ bkg,
                   float* __restrict__ out) {
    extern __shared__ float sm[];
    float* Ws = sm;                       // 64 * 256
    float* Xs = sm + 64 * 256;            // BT * 256
    float* Bs = Xs + BT * 256;            // 64

    const int n     = blockIdx.x;         // chunk id 0..1023
    const int btile = blockIdx.y;         // 0..1
    const int ch    = n >> 5;
    const int cw    = n & 31;
    const int tid   = threadIdx.x;

    // ---- load W[n] (64x256) into smem, K-contiguous rows, quad-XOR swizzle ----
    {
        const float4* Wg4 = reinterpret_cast<const float4*>(Wg + (size_t)n * 64 * 256);
        #pragma unroll
        for (int e = tid; e < 64 * 64; e += NTHREADS) {
            int o  = e >> 6;
            int k  = (e & 63) << 2;
            int ks = k ^ swz(o);
            *reinterpret_cast<float4*>(&Ws[o * 256 + ks]) = Wg4[e];
        }
    }
    if (tid < 64) Bs[tid] = bkg[n * 64 + tid];

    // ---- load X tile: 128 batches x 256 k (chunk gather, 64B-row coalesced) ----
    {
        const float* xbase = xg + (size_t)(ch * 16) * 512 + cw * 16;
        #pragma unroll
        for (int e = tid; e < BT * 64; e += NTHREADS) {
            int b  = e >> 6;
            int r  = e & 63;
            int i  = r >> 2;
            int j4 = (r & 3) << 2;
            int bglob = btile * BT + b;
            float4 v = *reinterpret_cast<const float4*>(
                xbase + (size_t)bglob * 262144 + i * 512 + j4);
            *reinterpret_cast<float4*>(&Xs[b * 256 + (i << 4) + j4]) = v;
        }
    }
    __syncthreads();

    // ---- compute: thread = (bgroup of 8 batches) x (og group of 4 outputs) ----
    const int og     = tid & 15;   // 16 output groups of 4  -> 64 outputs
    const int bgroup = tid >> 4;   // 16 batch groups of 8   -> 128 batches
    const int xc     = (og & 7) << 2;   // xor constant for this thread's W rows

    const float* xp = Xs + bgroup * 8 * 256;
    const float* wp = Ws + og * 4 * 256;

    unsigned long long acc[8][4];
    #pragma unroll
    for (int i = 0; i < 8; i++)
        #pragma unroll
        for (int j = 0; j < 4; j++) acc[i][j] = 0ULL;

    #pragma unroll 1
    for (int k = 0; k < 256; k += 4) {
        unsigned long long xv[8][2];
        unsigned long long wv[4][2];
        #pragma unroll
        for (int bc = 0; bc < 8; bc++) {
            ulonglong2 t = *reinterpret_cast<const ulonglong2*>(xp + bc * 256 + k);
            xv[bc][0] = t.x; xv[bc][1] = t.y;
        }
        const int ks = k ^ xc;
        #pragma unroll
        for (int oc = 0; oc < 4; oc++) {
            ulonglong2 t = *reinterpret_cast<const ulonglong2*>(wp + oc * 256 + ks);
            wv[oc][0] = t.x; wv[oc][1] = t.y;
        }
        #pragma unroll
        for (int bc = 0; bc < 8; bc++)
            #pragma unroll
            for (int oc = 0; oc < 4; oc++) {
                fma2(acc[bc][oc], xv[bc][0], wv[oc][0]);
                fma2(acc[bc][oc], xv[bc][1], wv[oc][1]);
            }
    }

    // ---- epilogue: horizontal add lanes + bias + relu, scatter to out ----
    const int oi = og >> 1;
    const int ojb = (og & 1) << 2;
    float* obase = out + (size_t)(btile * BT) * 65536
                       + (ch * 8 + oi) * 256 + cw * 8 + ojb;
    #pragma unroll
    for (int bc = 0; bc < 8; bc++) {
        float4 v;
        float* vv = &v.x;
        #pragma unroll
        for (int oc = 0; oc < 4; oc++) {
            float2 f = unpack2(acc[bc][oc]);
            float s = f.x + f.y + Bs[og * 4 + oc];
            vv[oc] = fmaxf(s, 0.0f);
        }
        int bl = bgroup * 8 + bc;
        *reinterpret_cast<float4*>(obase + (size_t)bl * 65536) = v;
    }
}

extern "C" void kernel_launch(void* const* d_in, const int* in_sizes, int n_in,
                              void* d_out, int out_size) {
    const float* x  = (const float*)d_in[0];   // [256,512,512]
    const float* Wk = (const float*)d_in[1];   // [1024,64,256]
    const float* bk = (const float*)d_in[2];   // [1024,64]
    float* out = (float*)d_out;                // [256, 65536]

    const size_t smem_bytes = (64 * 256 + BT * 256 + 64) * sizeof(float); // 196,864 B
    cudaFuncSetAttribute(compression_kernel,
                         cudaFuncAttributeMaxDynamicSharedMemorySize,
                         (int)smem_bytes);

    dim3 grid(1024, 2);
    compression_kernel<<<grid, NTHREADS, smem_bytes>>>(x, Wk, bk, out);
}

// round 4
// speedup vs baseline: 1.3531x; 1.3531x over previous
#include <cuda_runtime.h>
#include <cuda_bf16.h>
#include <cstdint>

// CompressionLayer grouped GEMM via SIMT tensor core (mma.sync bf16, HMMA).
// y[b,n,o] = relu( sum_k x[b,n,k] * Wk[n,o,k] + bk[n,o] )
// Block = (btile of 32 batches, chunk n). D[32,64] = X[32,256] * W[64,256]^T
// 3-split bf16: xh*wh + xh*wl + xl*wh, fp32 accumulation.
// smem ~96.4KB -> 2 CTAs/SM. grid(8,1024): CTAs sharing W[n] are adjacent.

#define NTHREADS 256
#define BT 32

// smem byte offsets (rows are 512B = 256 bf16, XOR-quad swizzled)
#define S_XH   0        // 32 x 512  = 16384
#define S_XL   16384
#define S_WH   32768    // 64 x 512  = 32768
#define S_WL   65536
#define S_BIAS 98304    // 64 f32
#define S_TOTAL 98688

static __device__ __forceinline__ uint32_t smem_u32(const void* p) {
    uint32_t a;
    asm("{ .reg .u64 t; cvta.to.shared.u64 t, %1; cvt.u32.u64 %0, t; }"
        : "=r"(a) : "l"(p));
    return a;
}

static __device__ __forceinline__ uint32_t lds32(uint32_t addr) {
    uint32_t v;
    asm volatile("ld.shared.b32 %0, [%1];" : "=r"(v) : "r"(addr));
    return v;
}

static __device__ __forceinline__ void ldmatrix_x4(uint32_t& a0, uint32_t& a1,
                                                   uint32_t& a2, uint32_t& a3,
                                                   uint32_t addr) {
    asm volatile("ldmatrix.sync.aligned.m8n8.x4.shared.b16 {%0,%1,%2,%3}, [%4];"
                 : "=r"(a0), "=r"(a1), "=r"(a2), "=r"(a3) : "r"(addr));
}

static __device__ __forceinline__ void mma16816(float* c, uint32_t a0, uint32_t a1,
                                                uint32_t a2, uint32_t a3,
                                                uint32_t b0, uint32_t b1) {
    asm volatile(
        "mma.sync.aligned.m16n8k16.row.col.f32.bf16.bf16.f32 "
        "{%0,%1,%2,%3}, {%4,%5,%6,%7}, {%8,%9}, {%0,%1,%2,%3};"
        : "+f"(c[0]), "+f"(c[1]), "+f"(c[2]), "+f"(c[3])
        : "r"(a0), "r"(a1), "r"(a2), "r"(a3), "r"(b0), "r"(b1));
}

// split f32x4 into bf16 hi/lo and store 8B each into swizzled smem row
static __device__ __forceinline__ void cvt_store(char* sm, int off_hi, int off_lo,
                                                 int row, int k, float4 v) {
    __nv_bfloat162 h01 = __floats2bfloat162_rn(v.x, v.y);
    __nv_bfloat162 h23 = __floats2bfloat162_rn(v.z, v.w);
    float lx = v.x - __bfloat162float(h01.x);
    float ly = v.y - __bfloat162float(h01.y);
    float lz = v.z - __bfloat162float(h23.x);
    float lw = v.w - __bfloat162float(h23.y);
    __nv_bfloat162 l01 = __floats2bfloat162_rn(lx, ly);
    __nv_bfloat162 l23 = __floats2bfloat162_rn(lz, lw);
    int col  = k * 2;                               // byte col, multiple of 8
    int phys = row * 512 + (col ^ ((row & 7) << 4)); // quad-XOR swizzle
    *reinterpret_cast<uint2*>(sm + off_hi + phys) =
        make_uint2(*(uint32_t*)&h01, *(uint32_t*)&h23);
    *reinterpret_cast<uint2*>(sm + off_lo + phys) =
        make_uint2(*(uint32_t*)&l01, *(uint32_t*)&l23);
}

__global__ void __launch_bounds__(NTHREADS, 2)
compression_mma_kernel(const float* __restrict__ xg,
                       const float* __restrict__ Wg,
                       const float* __restrict__ bkg,
                       float* __restrict__ out) {
    extern __shared__ char sm[];
    const uint32_t sb = smem_u32(sm);
    const int tid = threadIdx.x;

    const int btile = blockIdx.x;      // 0..7   (fastest -> W[n] shared in-wave)
    const int n     = blockIdx.y;      // 0..1023
    const int ch    = n >> 5;
    const int cw    = n & 31;

    // ---- W[n]: 64x256 f32 -> bf16 hi/lo (16 float4 per thread, MLP 16) ----
    {
        const float4* Wg4 = reinterpret_cast<const float4*>(Wg + (size_t)n * 64 * 256);
        #pragma unroll
        for (int it = 0; it < 16; ++it) {
            int e  = tid + it * NTHREADS;   // 0..4095
            int o  = e >> 6;
            int k4 = (e & 63) << 2;
            cvt_store(sm, S_WH, S_WL, o, k4, Wg4[e]);
        }
    }
    if (tid < 64)
        reinterpret_cast<float*>(sm + S_BIAS)[tid] = bkg[n * 64 + tid];

    // ---- X tile: 32 batches x 256 k, chunk gather (8 float4/thread) ----
    {
        const float* xbase = xg + (size_t)(ch * 16) * 512 + cw * 16;
        #pragma unroll
        for (int it = 0; it < 8; ++it) {
            int e  = tid + it * NTHREADS;   // 0..2047
            int b  = e >> 6;
            int r  = e & 63;
            int i  = r >> 2;
            int j4 = (r & 3) << 2;
            int bglob = btile * BT + b;
            float4 v = *reinterpret_cast<const float4*>(
                xbase + (size_t)bglob * 262144 + i * 512 + j4);
            cvt_store(sm, S_XH, S_XL, b, i * 16 + j4, v);
        }
    }
    __syncthreads();

    // ---- compute: 8 warps, warp tile m16 x n16 (2 n8 mma tiles) ----
    const int wid = tid >> 5;
    const int lid = tid & 31;
    const int wm  = (wid & 1) << 4;     // 0 / 16
    const int wn  = (wid >> 1) << 4;    // 0 / 16 / 32 / 48
    const int g   = lid >> 2;
    const int t   = lid & 3;

    const int arow = wm + (lid & 15);
    const uint32_t a_base = sb + arow * 512;
    const uint32_t a_sw   = (uint32_t)(arow & 7) << 4;
    const uint32_t a_coff = (uint32_t)(lid >> 4) << 4;  // 0 / 16

    const int o0 = wn + g;
    const int o1 = wn + 8 + g;
    const uint32_t b0_base = sb + o0 * 512;
    const uint32_t b1_base = sb + o1 * 512;
    const uint32_t b0_sw   = (uint32_t)(o0 & 7) << 4;
    const uint32_t b1_sw   = (uint32_t)(o1 & 7) << 4;
    const uint32_t bt_off  = 4 * t;

    float acc[2][4] = {{0.f, 0.f, 0.f, 0.f}, {0.f, 0.f, 0.f, 0.f}};

    const uint32_t a_off_s[3] = {S_XH, S_XH, S_XL};
    const uint32_t b_off_s[3] = {S_WH, S_WL, S_WH};

    #pragma unroll
    for (int sp = 0; sp < 3; ++sp) {
        const uint32_t abase = a_base + a_off_s[sp];
        const uint32_t bb0   = b0_base + b_off_s[sp];
        const uint32_t bb1   = b1_base + b_off_s[sp];
        #pragma unroll
        for (int s = 0; s < 16; ++s) {
            uint32_t colA = ((uint32_t)s << 5) | a_coff;
            uint32_t a0, a1, a2, a3;
            ldmatrix_x4(a0, a1, a2, a3, abase + (colA ^ a_sw));

            uint32_t colB = ((uint32_t)s << 5) + bt_off;
            uint32_t r00 = lds32(bb0 + (colB ^ b0_sw));
            uint32_t r01 = lds32(bb0 + ((colB + 16) ^ b0_sw));
            uint32_t r10 = lds32(bb1 + (colB ^ b1_sw));
            uint32_t r11 = lds32(bb1 + ((colB + 16) ^ b1_sw));

            mma16816(acc[0], a0, a1, a2, a3, r00, r01);
            mma16816(acc[1], a0, a1, a2, a3, r10, r11);
        }
    }

    // ---- epilogue: bias + relu, scatter ----
    const float* Bs = reinterpret_cast<const float*>(sm + S_BIAS);
    #pragma unroll
    for (int nt = 0; nt < 2; ++nt) {
        int ob  = wn + nt * 8;          // multiple of 8
        int oi  = ob >> 3;
        int oj  = 2 * t;
        float bi0 = Bs[ob + oj];
        float bi1 = Bs[ob + oj + 1];

        size_t colofs = (size_t)(ch * 8 + oi) * 256 + cw * 8 + oj;
        int bg0 = btile * BT + wm + g;
        float2 v0 = make_float2(fmaxf(acc[nt][0] + bi0, 0.f),
                                fmaxf(acc[nt][1] + bi1, 0.f));
        *reinterpret_cast<float2*>(out + (size_t)bg0 * 65536 + colofs) = v0;

        int bg1 = bg0 + 8;
        float2 v1 = make_float2(fmaxf(acc[nt][2] + bi0, 0.f),
                                fmaxf(acc[nt][3] + bi1, 0.f));
        *reinterpret_cast<float2*>(out + (size_t)bg1 * 65536 + colofs) = v1;
    }
}

extern "C" void kernel_launch(void* const* d_in, const int* in_sizes, int n_in,
                              void* d_out, int out_size) {
    const float* x  = (const float*)d_in[0];   // [256,512,512]
    const float* Wk = (const float*)d_in[1];   // [1024,64,256]
    const float* bk = (const float*)d_in[2];   // [1024,64]
    float* out = (float*)d_out;                // [256, 65536]

    cudaFuncSetAttribute(compression_mma_kernel,
                         cudaFuncAttributeMaxDynamicSharedMemorySize, S_TOTAL);

    dim3 grid(8, 1024);   // btile fastest: CTAs sharing W[n] adjacent in wave
    compression_mma_kernel<<<grid, NTHREADS, S_TOTAL>>>(x, Wk, bk, out);
}